// round 1
// baseline (speedup 1.0000x reference)
#include <cuda_runtime.h>

// Problem constants
#define BB 2
#define SS 2048
#define DD 1024
#define HH 16
#define HD 64
#define N3 (3 * DD)     // 3072
#define MROWS (BB * SS) // 4096

// d_out layout (concatenated flattened outputs, in reference return order)
#define A_SZ   ((long long)BB * SS * DD)           // 4,194,304
#define P_HALF ((long long)BB * HH * SS * HD)      // 4,194,304
#define P_OFF  (A_SZ)
#define ATTN_OFF (A_SZ + 2 * P_HALF)               // 12,582,912

// Scratch (device globals — no allocations allowed)
__device__ float g_q[BB * HH * SS * HD];   // q in [B,H,S,hd]
__device__ float g_ah[MROWS * DD];         // merged-head attention output [B*S, D]

// ---------------------------------------------------------------------------
// Kernel 1: QKV projection. x[4096,1024] @ w_attn[1024,3072] + b_attn.
// 128x64 tile per block, 256 threads, 8x4 per thread, K-tile 16.
// Epilogue scatters q -> g_q, k/v -> present region of d_out ([B,H,S,hd]).
// ---------------------------------------------------------------------------
__global__ __launch_bounds__(256) void qkv_gemm(const float* __restrict__ x,
                                                const float* __restrict__ w,
                                                const float* __restrict__ bias,
                                                float* __restrict__ out) {
    __shared__ float As[128][17];
    __shared__ float Bs[16][68];
    const int tid = threadIdx.x;
    const int tx = tid & 15, ty = tid >> 4;
    const int rbase = blockIdx.y * 128;
    const int nbase = blockIdx.x * 64;

    float acc[8][4];
#pragma unroll
    for (int i = 0; i < 8; i++)
#pragma unroll
        for (int j = 0; j < 4; j++) acc[i][j] = 0.f;

    for (int kb = 0; kb < DD; kb += 16) {
        // load A tile: 128x16
#pragma unroll
        for (int i = tid; i < 512; i += 256) {
            int r = i >> 2, c = (i & 3) << 2;
            float4 v = *(const float4*)&x[(long long)(rbase + r) * DD + kb + c];
            As[r][c + 0] = v.x; As[r][c + 1] = v.y;
            As[r][c + 2] = v.z; As[r][c + 3] = v.w;
        }
        // load B tile: 16x64
        {
            int k = tid >> 4, c = (tid & 15) << 2;
            *(float4*)&Bs[k][c] = *(const float4*)&w[(long long)(kb + k) * N3 + nbase + c];
        }
        __syncthreads();
#pragma unroll
        for (int k = 0; k < 16; k++) {
            float a[8];
#pragma unroll
            for (int i = 0; i < 8; i++) a[i] = As[ty * 8 + i][k];
            float4 bv = *(float4*)&Bs[k][tx * 4];
#pragma unroll
            for (int i = 0; i < 8; i++) {
                acc[i][0] += a[i] * bv.x;
                acc[i][1] += a[i] * bv.y;
                acc[i][2] += a[i] * bv.z;
                acc[i][3] += a[i] * bv.w;
            }
        }
        __syncthreads();
    }

    // epilogue: bias + scatter
    float bj[4];
#pragma unroll
    for (int j = 0; j < 4; j++) bj[j] = bias[nbase + tx * 4 + j];

#pragma unroll
    for (int i = 0; i < 8; i++) {
        int row = rbase + ty * 8 + i;
        int b = row >> 11, s = row & 2047;
#pragma unroll
        for (int j = 0; j < 4; j++) {
            int col = nbase + tx * 4 + j;
            float v = acc[i][j] + bj[j];
            int which = col >> 10;
            int d = col & 1023;
            int h = d >> 6, e = d & 63;
            long long idx = (((long long)(b * HH + h)) * SS + s) * HD + e;
            if (which == 0)      g_q[idx] = v;
            else if (which == 1) out[P_OFF + idx] = v;            // present[0] = k
            else                 out[P_OFF + P_HALF + idx] = v;   // present[1] = v
        }
    }
}

// ---------------------------------------------------------------------------
// Kernel 2: causal attention for one (b, h, 64-query-row tile).
// Phase A: denominators (no max-shift needed: scores are O(1)).
// Phase B: recompute scores, write normalized attn, accumulate attn@V.
// ---------------------------------------------------------------------------
#define SMP 68
#define ATTN_SMEM (4 * 64 * SMP * 4 + 64 * 4)

__global__ __launch_bounds__(256) void attn_kernel(float* __restrict__ out) {
    extern __shared__ float sm[];
    float* sQ = sm;
    float* sK = sm + 64 * SMP;
    float* sV = sm + 2 * 64 * SMP;
    float* sS = sm + 3 * 64 * SMP;
    float* rs = sm + 4 * 64 * SMP;

    const int tid = threadIdx.x;
    const int tx = tid & 15, ty = tid >> 4;
    const int qt = blockIdx.x, h = blockIdx.y, b = blockIdx.z;
    const int qbase = qt * 64;
    const long long headoff = ((long long)(b * HH + h)) * SS * HD;

    const float* qptr = g_q + headoff + (long long)qbase * HD;
    const float* kptr = out + P_OFF + headoff;
    const float* vptr = out + P_OFF + P_HALF + headoff;
    float* attn_out = out + ATTN_OFF + ((long long)(b * HH + h)) * SS * SS;

    // load Q tile (64x64)
#pragma unroll
    for (int i = tid; i < 1024; i += 256) {
        int r = i >> 4, c = (i & 15) << 2;
        *(float4*)&sQ[r * SMP + c] = *(const float4*)&qptr[r * HD + c];
    }

    const int r0 = ty * 4;
    const int c0 = tx * 4;

    // ---------------- Phase A: row denominators ----------------
    float rpart[4] = {0.f, 0.f, 0.f, 0.f};
    for (int kt = 0; kt <= qt; kt++) {
        __syncthreads();
#pragma unroll
        for (int i = tid; i < 1024; i += 256) {
            int r = i >> 4, c = (i & 15) << 2;
            *(float4*)&sK[r * SMP + c] = *(const float4*)&kptr[(kt * 64 + r) * HD + c];
        }
        __syncthreads();

        float acc[4][4];
#pragma unroll
        for (int i = 0; i < 4; i++)
#pragma unroll
            for (int j = 0; j < 4; j++) acc[i][j] = 0.f;

#pragma unroll 4
        for (int d = 0; d < 64; d++) {
            float qf[4], kf[4];
#pragma unroll
            for (int i = 0; i < 4; i++) qf[i] = sQ[(r0 + i) * SMP + d];
#pragma unroll
            for (int j = 0; j < 4; j++) kf[j] = sK[(c0 + j) * SMP + d];
#pragma unroll
            for (int i = 0; i < 4; i++)
#pragma unroll
                for (int j = 0; j < 4; j++) acc[i][j] += qf[i] * kf[j];
        }
        const bool diag = (kt == qt);
#pragma unroll
        for (int i = 0; i < 4; i++)
#pragma unroll
            for (int j = 0; j < 4; j++) {
                float e = (diag && (c0 + j > r0 + i)) ? 0.f
                                                      : __expf(acc[i][j] * 0.125f);
                rpart[i] += e;
            }
    }
    // reduce across the 16 tx lanes (same ty stays within half-warp)
#pragma unroll
    for (int i = 0; i < 4; i++) {
        rpart[i] += __shfl_xor_sync(0xFFFFFFFFu, rpart[i], 1);
        rpart[i] += __shfl_xor_sync(0xFFFFFFFFu, rpart[i], 2);
        rpart[i] += __shfl_xor_sync(0xFFFFFFFFu, rpart[i], 4);
        rpart[i] += __shfl_xor_sync(0xFFFFFFFFu, rpart[i], 8);
    }
    if (tx == 0) {
#pragma unroll
        for (int i = 0; i < 4; i++) rs[r0 + i] = rpart[i];
    }
    __syncthreads();
    float rinv[4];
#pragma unroll
    for (int i = 0; i < 4; i++) rinv[i] = 1.0f / rs[r0 + i];

    // ---------------- Phase B: write attn + attn@V ----------------
    float ao[4][4];
#pragma unroll
    for (int i = 0; i < 4; i++)
#pragma unroll
        for (int j = 0; j < 4; j++) ao[i][j] = 0.f;

    for (int kt = 0; kt <= qt; kt++) {
        __syncthreads();
#pragma unroll
        for (int i = tid; i < 2048; i += 256) {
            int r = (i >> 4) & 63, c = (i & 15) << 2;
            if (i < 1024)
                *(float4*)&sK[r * SMP + c] = *(const float4*)&kptr[(kt * 64 + r) * HD + c];
            else
                *(float4*)&sV[r * SMP + c] = *(const float4*)&vptr[(kt * 64 + r) * HD + c];
        }
        __syncthreads();

        float acc[4][4];
#pragma unroll
        for (int i = 0; i < 4; i++)
#pragma unroll
            for (int j = 0; j < 4; j++) acc[i][j] = 0.f;

#pragma unroll 4
        for (int d = 0; d < 64; d++) {
            float qf[4], kf[4];
#pragma unroll
            for (int i = 0; i < 4; i++) qf[i] = sQ[(r0 + i) * SMP + d];
#pragma unroll
            for (int j = 0; j < 4; j++) kf[j] = sK[(c0 + j) * SMP + d];
#pragma unroll
            for (int i = 0; i < 4; i++)
#pragma unroll
                for (int j = 0; j < 4; j++) acc[i][j] += qf[i] * kf[j];
        }
        const bool diag = (kt == qt);
#pragma unroll
        for (int i = 0; i < 4; i++) {
#pragma unroll
            for (int j = 0; j < 4; j++) {
                float e = (diag && (c0 + j > r0 + i)) ? 0.f
                                                      : __expf(acc[i][j] * 0.125f);
                acc[i][j] = e * rinv[i];
            }
            float4 av = make_float4(acc[i][0], acc[i][1], acc[i][2], acc[i][3]);
            *(float4*)&sS[(r0 + i) * SMP + c0] = av;
            *(float4*)&attn_out[(long long)(qbase + r0 + i) * SS + kt * 64 + c0] = av;
        }
        __syncthreads();

        // AV: ao[r][e] += sS[r][j] * sV[j][e]
#pragma unroll 2
        for (int j = 0; j < 64; j++) {
            float sv[4];
#pragma unroll
            for (int i = 0; i < 4; i++) sv[i] = sS[(r0 + i) * SMP + j];
            float4 vv = *(float4*)&sV[j * SMP + c0];
#pragma unroll
            for (int i = 0; i < 4; i++) {
                ao[i][0] += sv[i] * vv.x;
                ao[i][1] += sv[i] * vv.y;
                ao[i][2] += sv[i] * vv.z;
                ao[i][3] += sv[i] * vv.w;
            }
        }
    }

    // zero-fill strictly-upper attn tiles
    float4 z = make_float4(0.f, 0.f, 0.f, 0.f);
    for (int col = (qt + 1) * 64 + c0; col < SS; col += 64) {
#pragma unroll
        for (int i = 0; i < 4; i++)
            *(float4*)&attn_out[(long long)(qbase + r0 + i) * SS + col] = z;
    }

    // write merged-head output to scratch
#pragma unroll
    for (int i = 0; i < 4; i++) {
        float4 av = make_float4(ao[i][0], ao[i][1], ao[i][2], ao[i][3]);
        *(float4*)&g_ah[((long long)(b * SS + qbase + r0 + i)) * DD + h * HD + c0] = av;
    }
}

// ---------------------------------------------------------------------------
// Kernel 3: output projection. g_ah[4096,1024] @ w_proj[1024,1024] + b_proj.
// ---------------------------------------------------------------------------
__global__ __launch_bounds__(256) void proj_gemm(const float* __restrict__ w,
                                                 const float* __restrict__ bias,
                                                 float* __restrict__ out) {
    __shared__ float As[128][17];
    __shared__ float Bs[16][68];
    const int tid = threadIdx.x;
    const int tx = tid & 15, ty = tid >> 4;
    const int rbase = blockIdx.y * 128;
    const int nbase = blockIdx.x * 64;

    float acc[8][4];
#pragma unroll
    for (int i = 0; i < 8; i++)
#pragma unroll
        for (int j = 0; j < 4; j++) acc[i][j] = 0.f;

    for (int kb = 0; kb < DD; kb += 16) {
#pragma unroll
        for (int i = tid; i < 512; i += 256) {
            int r = i >> 2, c = (i & 3) << 2;
            float4 v = *(const float4*)&g_ah[(long long)(rbase + r) * DD + kb + c];
            As[r][c + 0] = v.x; As[r][c + 1] = v.y;
            As[r][c + 2] = v.z; As[r][c + 3] = v.w;
        }
        {
            int k = tid >> 4, c = (tid & 15) << 2;
            *(float4*)&Bs[k][c] = *(const float4*)&w[(long long)(kb + k) * DD + nbase + c];
        }
        __syncthreads();
#pragma unroll
        for (int k = 0; k < 16; k++) {
            float a[8];
#pragma unroll
            for (int i = 0; i < 8; i++) a[i] = As[ty * 8 + i][k];
            float4 bv = *(float4*)&Bs[k][tx * 4];
#pragma unroll
            for (int i = 0; i < 8; i++) {
                acc[i][0] += a[i] * bv.x;
                acc[i][1] += a[i] * bv.y;
                acc[i][2] += a[i] * bv.z;
                acc[i][3] += a[i] * bv.w;
            }
        }
        __syncthreads();
    }

    float bj[4];
#pragma unroll
    for (int j = 0; j < 4; j++) bj[j] = bias[nbase + tx * 4 + j];
#pragma unroll
    for (int i = 0; i < 8; i++) {
        int row = rbase + ty * 8 + i;
        float4 v = make_float4(acc[i][0] + bj[0], acc[i][1] + bj[1],
                               acc[i][2] + bj[2], acc[i][3] + bj[3]);
        *(float4*)&out[(long long)row * DD + nbase + tx * 4] = v;
    }
}

// ---------------------------------------------------------------------------
extern "C" void kernel_launch(void* const* d_in, const int* in_sizes, int n_in,
                              void* d_out, int out_size) {
    const float* x      = (const float*)d_in[0];
    const float* w_attn = (const float*)d_in[1];
    const float* b_attn = (const float*)d_in[2];
    const float* w_proj = (const float*)d_in[3];
    const float* b_proj = (const float*)d_in[4];
    float* out = (float*)d_out;

    cudaFuncSetAttribute(attn_kernel, cudaFuncAttributeMaxDynamicSharedMemorySize,
                         ATTN_SMEM);

    // 1) QKV projection: writes g_q and present(k,v) in d_out
    qkv_gemm<<<dim3(N3 / 64, MROWS / 128), 256>>>(x, w_attn, b_attn, out);

    // 2) attention: writes attn region of d_out and g_ah
    attn_kernel<<<dim3(SS / 64, HH, BB), 256, ATTN_SMEM>>>(out);

    // 3) output projection: writes a region of d_out
    proj_gemm<<<dim3(DD / 64, MROWS / 128), 256>>>(w_proj, b_proj, out);
}